// round 12
// baseline (speedup 1.0000x reference)
#include <cuda_runtime.h>
#include <cuda_fp16.h>

// LightGCN, y-space formulation with fp16 intermediates.
//   y_k = dinv ⊙ x_k  (y0 = dinv ⊙ emb)
//   S[s]     = sum_{e: src=s} y_k[dst(e)]
//   x_{k+1}  = dinv ⊙ S          y_{k+1} = dinv^2 ⊙ S
//   out = (emb + x1 + x2 + x3)/4, emb term exact fp32,
//         x1 = sqrt(deg) * y1, x2 = sqrt(deg) * y2.
//
// Hist atomics are fire-and-forget (REDG path). Scatter uses returning
// cursor atomics but is packed into FEW blocks (32 edges/thread, ~244
// blocks ≈ 1.6 slots/SM) so the co-scheduled y0 convert gets the
// remaining ~940 block slots and hides inside the atomic window
// (R11 lesson: latency-bound work must occupy few slots).

#define D 128
#define MAX_NODES 160000
#define MAX_EDGES 2200000
#define SCAN_BLK 1024

struct __align__(8) Half4 {
    __half2 h01;
    __half2 h23;
};

__device__ int   g_deg[MAX_NODES];          // zeroed at load; self-zeroed in scan23
__device__ int   g_rowptr[MAX_NODES + 1];
__device__ int   g_cursor[MAX_NODES];
__device__ float g_dinv[MAX_NODES];
__device__ float g_rinv[MAX_NODES];         // sqrt(deg) (0 if deg==0)
__device__ int   g_cols[MAX_EDGES];
__device__ Half4 g_y0[(size_t)MAX_NODES * 32];
__device__ Half4 g_y1[(size_t)MAX_NODES * 32];
__device__ Half4 g_y2[(size_t)MAX_NODES * 32];
__device__ int   g_bsum[256];

// ---------------------------------------------------------------- setup ----

// degree histogram, 4 edges per thread; return value DISCARDED (REDG)
__global__ void hist_kernel(const int* __restrict__ src, int nE) {
    int t = blockIdx.x * blockDim.x + threadIdx.x;
    int e = t * 4;
    if (e + 3 < nE) {
        int4 s4 = __ldg((const int4*)(src + e));
        atomicAdd(&g_deg[s4.x], 1);
        atomicAdd(&g_deg[s4.y], 1);
        atomicAdd(&g_deg[s4.z], 1);
        atomicAdd(&g_deg[s4.w], 1);
    } else {
        for (int k = e; k < nE; k++) atomicAdd(&g_deg[src[k]], 1);
    }
}

// per-1024-block exclusive scan of g_deg into g_rowptr; block sums to g_bsum
__global__ void scan1_kernel(int n) {
    __shared__ int sh[SCAN_BLK];
    int tid = threadIdx.x;
    int i = blockIdx.x * SCAN_BLK + tid;
    int v = (i < n) ? g_deg[i] : 0;
    sh[tid] = v;
    __syncthreads();
    for (int off = 1; off < SCAN_BLK; off <<= 1) {
        int t = (tid >= off) ? sh[tid - off] : 0;
        __syncthreads();
        sh[tid] += t;
        __syncthreads();
    }
    if (i < n) g_rowptr[i] = sh[tid] - v;
    if (tid == SCAN_BLK - 1) g_bsum[blockIdx.x] = sh[tid];
}

// merged scan2+scan3: block-prefix + cursor init + dinv/rinv; self-zero g_deg
__global__ void scan23_kernel(int n, int nb) {
    __shared__ int sh[256];
    int tid = threadIdx.x;
    int i = blockIdx.x * 256 + tid;
    int chunk = (blockIdx.x * 256) >> 10;          // same for whole block

    int b = (tid < nb) ? g_bsum[tid] : 0;

    sh[tid] = (tid < chunk) ? b : 0;
    __syncthreads();
    for (int off = 128; off > 0; off >>= 1) {
        if (tid < off) sh[tid] += sh[tid + off];
        __syncthreads();
    }
    int prefix = sh[0];
    __syncthreads();

    sh[tid] = b;
    __syncthreads();
    for (int off = 128; off > 0; off >>= 1) {
        if (tid < off) sh[tid] += sh[tid + off];
        __syncthreads();
    }
    int total = sh[0];

    if (i < n) {
        int rp = g_rowptr[i] + prefix;
        g_rowptr[i] = rp;
        g_cursor[i] = rp;
        int d = g_deg[i];
        float fd = (float)d;
        g_dinv[i] = (d > 0) ? rsqrtf(fd) : 0.0f;
        g_rinv[i] = (d > 0) ? sqrtf(fd) : 0.0f;
        g_deg[i] = 0;                                // ready for next replay
    }
    if (i == 0) g_rowptr[n] = total;
}

// scatter + y0 convert with DISJOINT thread ranges:
//   threads [0, nscat)   : 32 edges each (4 batches of 8 independent atomics)
//                          -> only ~244 blocks, leaving slots for convert
//   threads [nscat, ...) : one Half4 convert each
__global__ void scatcvt_kernel(const float* __restrict__ uw,
                               const float* __restrict__ iw,
                               const int* __restrict__ src,
                               const int* __restrict__ dst,
                               int nE, int nscat, int num_users, int n_nodes) {
    int i = blockIdx.x * blockDim.x + threadIdx.x;

    if (i < nscat) {
        int e = i * 32;
        if (e + 31 < nE) {
#pragma unroll
            for (int b = 0; b < 4; b++) {
                int eb = e + b * 8;
                int4 sa = __ldg((const int4*)(src + eb));
                int4 sb = __ldg((const int4*)(src + eb + 4));
                int4 da = __ldg((const int4*)(dst + eb));
                int4 db = __ldg((const int4*)(dst + eb + 4));
                int p0 = atomicAdd(&g_cursor[sa.x], 1);
                int p1 = atomicAdd(&g_cursor[sa.y], 1);
                int p2 = atomicAdd(&g_cursor[sa.z], 1);
                int p3 = atomicAdd(&g_cursor[sa.w], 1);
                int p4 = atomicAdd(&g_cursor[sb.x], 1);
                int p5 = atomicAdd(&g_cursor[sb.y], 1);
                int p6 = atomicAdd(&g_cursor[sb.z], 1);
                int p7 = atomicAdd(&g_cursor[sb.w], 1);
                g_cols[p0] = da.x;
                g_cols[p1] = da.y;
                g_cols[p2] = da.z;
                g_cols[p3] = da.w;
                g_cols[p4] = db.x;
                g_cols[p5] = db.y;
                g_cols[p6] = db.z;
                g_cols[p7] = db.w;
            }
        } else {
            for (int k = e; k < nE; k++) {
                int pos = atomicAdd(&g_cursor[src[k]], 1);
                g_cols[pos] = dst[k];
            }
        }
        return;
    }

    int j = i - nscat;
    if (j >= n_nodes * 32) return;
    int node = j >> 5, lane = j & 31;
    const float4* srcp = (const float4*)((node < num_users)
                            ? uw + (size_t)node * D
                            : iw + (size_t)(node - num_users) * D);
    float4 f = srcp[lane];
    float dv = g_dinv[node];
    Half4 r;
    r.h01 = __floats2half2_rn(f.x * dv, f.y * dv);
    r.h23 = __floats2half2_rn(f.z * dv, f.w * dv);
    g_y0[j] = r;
}

// ----------------------------------------------------------------- SpMM ----
// One warp per row; lane owns dims [4*lane, 4*lane+4) as one Half4.
// Pure sum over neighbors (no per-edge scale).

__device__ __forceinline__ void acc_edge(Half4 r,
                                         float& a0, float& a1, float& a2, float& a3) {
    float2 f01 = __half22float2(r.h01);
    float2 f23 = __half22float2(r.h23);
    a0 += f01.x;
    a1 += f01.y;
    a2 += f23.x;
    a3 += f23.y;
}

__device__ __forceinline__ void gather_row(const Half4* __restrict__ xin,
                                           int start, int end, int lane,
                                           float& a0, float& a1, float& a2, float& a3) {
    int j = start;
    for (; j + 4 <= end; j += 4) {
        int c0 = __ldg(&g_cols[j]);
        int c1 = __ldg(&g_cols[j + 1]);
        int c2 = __ldg(&g_cols[j + 2]);
        int c3 = __ldg(&g_cols[j + 3]);
        Half4 r0 = xin[(size_t)c0 * 32 + lane];
        Half4 r1 = xin[(size_t)c1 * 32 + lane];
        Half4 r2 = xin[(size_t)c2 * 32 + lane];
        Half4 r3 = xin[(size_t)c3 * 32 + lane];
        acc_edge(r0, a0, a1, a2, a3);
        acc_edge(r1, a0, a1, a2, a3);
        acc_edge(r2, a0, a1, a2, a3);
        acc_edge(r3, a0, a1, a2, a3);
    }
    for (; j < end; j++) {
        int c = __ldg(&g_cols[j]);
        Half4 r = xin[(size_t)c * 32 + lane];
        acc_edge(r, a0, a1, a2, a3);
    }
}

// layers 1 & 2: gather y_{k-1} -> write y_k = dinv^2 * sum
__global__ void __launch_bounds__(256)
spmm_mid(int layer, int n_nodes) {
    int warp = (blockIdx.x * blockDim.x + threadIdx.x) >> 5;
    int lane = threadIdx.x & 31;
    if (warp >= n_nodes) return;

    const Half4* xin  = (layer == 1) ? g_y0 : g_y1;
    Half4*       xout = (layer == 1) ? g_y1 : g_y2;

    float dv = g_dinv[warp];
    float w2 = dv * dv;
    int start = __ldg(&g_rowptr[warp]);
    int end   = __ldg(&g_rowptr[warp + 1]);

    float a0 = 0.f, a1 = 0.f, a2 = 0.f, a3 = 0.f;
    gather_row(xin, start, end, lane, a0, a1, a2, a3);

    Half4 r;
    r.h01 = __floats2half2_rn(a0 * w2, a1 * w2);
    r.h23 = __floats2half2_rn(a2 * w2, a3 * w2);
    xout[(size_t)warp * 32 + lane] = r;
}

// layer 3: gather y2 -> x3 = dinv*sum; fuse out = (emb + x1 + x2 + x3)/4
// with x1 = rinv*y1, x2 = rinv*y2.
__global__ void __launch_bounds__(256)
spmm_last(const float* __restrict__ uw, const float* __restrict__ iw,
          int num_users, int n_nodes, float* __restrict__ out) {
    int warp = (blockIdx.x * blockDim.x + threadIdx.x) >> 5;
    int lane = threadIdx.x & 31;
    if (warp >= n_nodes) return;

    float dv = g_dinv[warp];
    float rv = g_rinv[warp];
    int start = __ldg(&g_rowptr[warp]);
    int end   = __ldg(&g_rowptr[warp + 1]);

    float a0 = 0.f, a1 = 0.f, a2 = 0.f, a3 = 0.f;
    gather_row(g_y2, start, end, lane, a0, a1, a2, a3);
    a0 *= dv; a1 *= dv; a2 *= dv; a3 *= dv;      // x3

    Half4 w1 = g_y1[(size_t)warp * 32 + lane];
    Half4 w2 = g_y2[(size_t)warp * 32 + lane];
    float2 p01 = __half22float2(w1.h01);
    float2 p23 = __half22float2(w1.h23);
    float2 q01 = __half22float2(w2.h01);
    float2 q23 = __half22float2(w2.h23);

    const float4* ep = (const float4*)((warp < num_users)
                          ? uw + (size_t)warp * D
                          : iw + (size_t)(warp - num_users) * D);
    float4 e = ep[lane];

    float4 o;
    o.x = (e.x + rv * (p01.x + q01.x) + a0) * 0.25f;
    o.y = (e.y + rv * (p01.y + q01.y) + a1) * 0.25f;
    o.z = (e.z + rv * (p23.x + q23.x) + a2) * 0.25f;
    o.w = (e.w + rv * (p23.y + q23.y) + a3) * 0.25f;
    ((float4*)(out + (size_t)warp * D))[lane] = o;
}

// --------------------------------------------------------------- launch ----

extern "C" void kernel_launch(void* const* d_in, const int* in_sizes, int n_in,
                              void* d_out, int out_size) {
    const float* uw = (const float*)d_in[0];
    const float* iw = (const float*)d_in[1];
    const int*   ei = (const int*)d_in[2];

    int num_users = in_sizes[0] / D;
    int num_items = in_sizes[1] / D;
    int n_nodes = num_users + num_items;
    int nE = in_sizes[2] / 2;
    const int* src = ei;
    const int* dst = ei + nE;
    float* out = (float*)d_out;

    // CSR build (g_deg arrives zeroed: module init / self-zero in scan23)
    hist_kernel<<<((nE + 3) / 4 + 255) / 256, 256>>>(src, nE);
    int nb = (n_nodes + SCAN_BLK - 1) / SCAN_BLK;
    scan1_kernel<<<nb, SCAN_BLK>>>(n_nodes);
    scan23_kernel<<<(n_nodes + 255) / 256, 256>>>(n_nodes, nb);

    int nscat = (nE + 31) / 32;
    int total_threads = nscat + n_nodes * 32;
    scatcvt_kernel<<<(total_threads + 255) / 256, 256>>>(uw, iw, src, dst, nE,
                                                         nscat, num_users, n_nodes);

    // 3 propagation layers
    int blocks = (n_nodes * 32 + 255) / 256;
    spmm_mid<<<blocks, 256>>>(1, n_nodes);
    spmm_mid<<<blocks, 256>>>(2, n_nodes);
    spmm_last<<<blocks, 256>>>(uw, iw, num_users, n_nodes, out);
}

// round 13
// speedup vs baseline: 1.0175x; 1.0175x over previous
#include <cuda_runtime.h>
#include <cuda_fp16.h>

// LightGCN, y-space formulation with fp16 intermediates.
//   y_k = dinv ⊙ x_k  (y0 = dinv ⊙ emb)
//   S[s]     = sum_{e: src=s} y_k[dst(e)]
//   x_{k+1}  = dinv ⊙ S          y_{k+1} = dinv^2 ⊙ S
//   out = (emb + x1 + x2 + x3)/4, emb term exact fp32,
//         x1 = sqrt(deg) * y1, x2 = sqrt(deg) * y2.
//
// Structure = R8 (best measured). SpMM gather unrolled x8 for MLP; last
// layer's own-row loads hoisted above the gather chain.

#define D 128
#define MAX_NODES 160000
#define MAX_EDGES 2200000
#define SCAN_BLK 1024

struct __align__(8) Half4 {
    __half2 h01;
    __half2 h23;
};

__device__ int   g_deg[MAX_NODES];          // zeroed at load; self-zeroed in scan23
__device__ int   g_rowptr[MAX_NODES + 1];
__device__ int   g_cursor[MAX_NODES];
__device__ float g_dinv[MAX_NODES];
__device__ float g_rinv[MAX_NODES];         // sqrt(deg) (0 if deg==0)
__device__ int   g_cols[MAX_EDGES];
__device__ Half4 g_y0[(size_t)MAX_NODES * 32];
__device__ Half4 g_y1[(size_t)MAX_NODES * 32];
__device__ Half4 g_y2[(size_t)MAX_NODES * 32];
__device__ int   g_bsum[256];

// ---------------------------------------------------------------- setup ----

// degree histogram, 4 edges per thread; return value DISCARDED (REDG)
__global__ void hist_kernel(const int* __restrict__ src, int nE) {
    int t = blockIdx.x * blockDim.x + threadIdx.x;
    int e = t * 4;
    if (e + 3 < nE) {
        int4 s4 = __ldg((const int4*)(src + e));
        atomicAdd(&g_deg[s4.x], 1);
        atomicAdd(&g_deg[s4.y], 1);
        atomicAdd(&g_deg[s4.z], 1);
        atomicAdd(&g_deg[s4.w], 1);
    } else {
        for (int k = e; k < nE; k++) atomicAdd(&g_deg[src[k]], 1);
    }
}

// per-1024-block exclusive scan of g_deg into g_rowptr; block sums to g_bsum
__global__ void scan1_kernel(int n) {
    __shared__ int sh[SCAN_BLK];
    int tid = threadIdx.x;
    int i = blockIdx.x * SCAN_BLK + tid;
    int v = (i < n) ? g_deg[i] : 0;
    sh[tid] = v;
    __syncthreads();
    for (int off = 1; off < SCAN_BLK; off <<= 1) {
        int t = (tid >= off) ? sh[tid - off] : 0;
        __syncthreads();
        sh[tid] += t;
        __syncthreads();
    }
    if (i < n) g_rowptr[i] = sh[tid] - v;
    if (tid == SCAN_BLK - 1) g_bsum[blockIdx.x] = sh[tid];
}

// merged scan2+scan3: block-prefix + cursor init + dinv/rinv; self-zero g_deg
__global__ void scan23_kernel(int n, int nb) {
    __shared__ int sh[256];
    int tid = threadIdx.x;
    int i = blockIdx.x * 256 + tid;
    int chunk = (blockIdx.x * 256) >> 10;          // same for whole block

    int b = (tid < nb) ? g_bsum[tid] : 0;

    sh[tid] = (tid < chunk) ? b : 0;
    __syncthreads();
    for (int off = 128; off > 0; off >>= 1) {
        if (tid < off) sh[tid] += sh[tid + off];
        __syncthreads();
    }
    int prefix = sh[0];
    __syncthreads();

    sh[tid] = b;
    __syncthreads();
    for (int off = 128; off > 0; off >>= 1) {
        if (tid < off) sh[tid] += sh[tid + off];
        __syncthreads();
    }
    int total = sh[0];

    if (i < n) {
        int rp = g_rowptr[i] + prefix;
        g_rowptr[i] = rp;
        g_cursor[i] = rp;
        int d = g_deg[i];
        float fd = (float)d;
        g_dinv[i] = (d > 0) ? rsqrtf(fd) : 0.0f;
        g_rinv[i] = (d > 0) ? sqrtf(fd) : 0.0f;
        g_deg[i] = 0;                                // ready for next replay
    }
    if (i == 0) g_rowptr[n] = total;
}

// scatter + y0 convert with DISJOINT thread ranges (R8 layout):
//   threads [0, nscat)   : 4 edges each (int4), independent atomics
//   threads [nscat, ...) : one Half4 convert each
__global__ void scatcvt_kernel(const float* __restrict__ uw,
                               const float* __restrict__ iw,
                               const int* __restrict__ src,
                               const int* __restrict__ dst,
                               int nE, int nscat, int num_users, int n_nodes) {
    int i = blockIdx.x * blockDim.x + threadIdx.x;

    if (i < nscat) {
        int e = i * 4;
        if (e + 3 < nE) {
            int4 s4 = __ldg((const int4*)(src + e));
            int4 d4 = __ldg((const int4*)(dst + e));
            int p0 = atomicAdd(&g_cursor[s4.x], 1);
            int p1 = atomicAdd(&g_cursor[s4.y], 1);
            int p2 = atomicAdd(&g_cursor[s4.z], 1);
            int p3 = atomicAdd(&g_cursor[s4.w], 1);
            g_cols[p0] = d4.x;
            g_cols[p1] = d4.y;
            g_cols[p2] = d4.z;
            g_cols[p3] = d4.w;
        } else {
            for (int k = e; k < nE; k++) {
                int pos = atomicAdd(&g_cursor[src[k]], 1);
                g_cols[pos] = dst[k];
            }
        }
        return;
    }

    int j = i - nscat;
    if (j >= n_nodes * 32) return;
    int node = j >> 5, lane = j & 31;
    const float4* srcp = (const float4*)((node < num_users)
                            ? uw + (size_t)node * D
                            : iw + (size_t)(node - num_users) * D);
    float4 f = srcp[lane];
    float dv = g_dinv[node];
    Half4 r;
    r.h01 = __floats2half2_rn(f.x * dv, f.y * dv);
    r.h23 = __floats2half2_rn(f.z * dv, f.w * dv);
    g_y0[j] = r;
}

// ----------------------------------------------------------------- SpMM ----
// One warp per row; lane owns dims [4*lane, 4*lane+4) as one Half4.
// Pure sum over neighbors; 8-edge unroll for MLP against L2 latency.

__device__ __forceinline__ void acc_edge(Half4 r,
                                         float& a0, float& a1, float& a2, float& a3) {
    float2 f01 = __half22float2(r.h01);
    float2 f23 = __half22float2(r.h23);
    a0 += f01.x;
    a1 += f01.y;
    a2 += f23.x;
    a3 += f23.y;
}

__device__ __forceinline__ void gather_row(const Half4* __restrict__ xin,
                                           int start, int end, int lane,
                                           float& a0, float& a1, float& a2, float& a3) {
    int j = start;
    for (; j + 8 <= end; j += 8) {
        int c0 = __ldg(&g_cols[j]);
        int c1 = __ldg(&g_cols[j + 1]);
        int c2 = __ldg(&g_cols[j + 2]);
        int c3 = __ldg(&g_cols[j + 3]);
        int c4 = __ldg(&g_cols[j + 4]);
        int c5 = __ldg(&g_cols[j + 5]);
        int c6 = __ldg(&g_cols[j + 6]);
        int c7 = __ldg(&g_cols[j + 7]);
        Half4 r0 = xin[(size_t)c0 * 32 + lane];
        Half4 r1 = xin[(size_t)c1 * 32 + lane];
        Half4 r2 = xin[(size_t)c2 * 32 + lane];
        Half4 r3 = xin[(size_t)c3 * 32 + lane];
        Half4 r4 = xin[(size_t)c4 * 32 + lane];
        Half4 r5 = xin[(size_t)c5 * 32 + lane];
        Half4 r6 = xin[(size_t)c6 * 32 + lane];
        Half4 r7 = xin[(size_t)c7 * 32 + lane];
        acc_edge(r0, a0, a1, a2, a3);
        acc_edge(r1, a0, a1, a2, a3);
        acc_edge(r2, a0, a1, a2, a3);
        acc_edge(r3, a0, a1, a2, a3);
        acc_edge(r4, a0, a1, a2, a3);
        acc_edge(r5, a0, a1, a2, a3);
        acc_edge(r6, a0, a1, a2, a3);
        acc_edge(r7, a0, a1, a2, a3);
    }
    for (; j < end; j++) {
        int c = __ldg(&g_cols[j]);
        Half4 r = xin[(size_t)c * 32 + lane];
        acc_edge(r, a0, a1, a2, a3);
    }
}

// layers 1 & 2: gather y_{k-1} -> write y_k = dinv^2 * sum
__global__ void __launch_bounds__(256)
spmm_mid(int layer, int n_nodes) {
    int warp = (blockIdx.x * blockDim.x + threadIdx.x) >> 5;
    int lane = threadIdx.x & 31;
    if (warp >= n_nodes) return;

    const Half4* xin  = (layer == 1) ? g_y0 : g_y1;
    Half4*       xout = (layer == 1) ? g_y1 : g_y2;

    float dv = g_dinv[warp];
    float w2 = dv * dv;
    int start = __ldg(&g_rowptr[warp]);
    int end   = __ldg(&g_rowptr[warp + 1]);

    float a0 = 0.f, a1 = 0.f, a2 = 0.f, a3 = 0.f;
    gather_row(xin, start, end, lane, a0, a1, a2, a3);

    Half4 r;
    r.h01 = __floats2half2_rn(a0 * w2, a1 * w2);
    r.h23 = __floats2half2_rn(a2 * w2, a3 * w2);
    xout[(size_t)warp * 32 + lane] = r;
}

// layer 3: gather y2 -> x3 = dinv*sum; fuse out = (emb + x1 + x2 + x3)/4
// with x1 = rinv*y1, x2 = rinv*y2. Own-row loads hoisted above the gather.
__global__ void __launch_bounds__(256)
spmm_last(const float* __restrict__ uw, const float* __restrict__ iw,
          int num_users, int n_nodes, float* __restrict__ out) {
    int warp = (blockIdx.x * blockDim.x + threadIdx.x) >> 5;
    int lane = threadIdx.x & 31;
    if (warp >= n_nodes) return;

    float dv = g_dinv[warp];
    float rv = g_rinv[warp];
    int start = __ldg(&g_rowptr[warp]);
    int end   = __ldg(&g_rowptr[warp + 1]);

    // issue own-row loads early; they complete under the gather chain
    Half4 w1 = g_y1[(size_t)warp * 32 + lane];
    Half4 w2 = g_y2[(size_t)warp * 32 + lane];
    const float4* ep = (const float4*)((warp < num_users)
                          ? uw + (size_t)warp * D
                          : iw + (size_t)(warp - num_users) * D);
    float4 e = ep[lane];

    float a0 = 0.f, a1 = 0.f, a2 = 0.f, a3 = 0.f;
    gather_row(g_y2, start, end, lane, a0, a1, a2, a3);
    a0 *= dv; a1 *= dv; a2 *= dv; a3 *= dv;      // x3

    float2 p01 = __half22float2(w1.h01);
    float2 p23 = __half22float2(w1.h23);
    float2 q01 = __half22float2(w2.h01);
    float2 q23 = __half22float2(w2.h23);

    float4 o;
    o.x = (e.x + rv * (p01.x + q01.x) + a0) * 0.25f;
    o.y = (e.y + rv * (p01.y + q01.y) + a1) * 0.25f;
    o.z = (e.z + rv * (p23.x + q23.x) + a2) * 0.25f;
    o.w = (e.w + rv * (p23.y + q23.y) + a3) * 0.25f;
    ((float4*)(out + (size_t)warp * D))[lane] = o;
}

// --------------------------------------------------------------- launch ----

extern "C" void kernel_launch(void* const* d_in, const int* in_sizes, int n_in,
                              void* d_out, int out_size) {
    const float* uw = (const float*)d_in[0];
    const float* iw = (const float*)d_in[1];
    const int*   ei = (const int*)d_in[2];

    int num_users = in_sizes[0] / D;
    int num_items = in_sizes[1] / D;
    int n_nodes = num_users + num_items;
    int nE = in_sizes[2] / 2;
    const int* src = ei;
    const int* dst = ei + nE;
    float* out = (float*)d_out;

    // CSR build (g_deg arrives zeroed: module init / self-zero in scan23)
    hist_kernel<<<((nE + 3) / 4 + 255) / 256, 256>>>(src, nE);
    int nb = (n_nodes + SCAN_BLK - 1) / SCAN_BLK;
    scan1_kernel<<<nb, SCAN_BLK>>>(n_nodes);
    scan23_kernel<<<(n_nodes + 255) / 256, 256>>>(n_nodes, nb);

    int nscat = (nE + 3) / 4;
    int total_threads = nscat + n_nodes * 32;
    scatcvt_kernel<<<(total_threads + 255) / 256, 256>>>(uw, iw, src, dst, nE,
                                                         nscat, num_users, n_nodes);

    // 3 propagation layers
    int blocks = (n_nodes * 32 + 255) / 256;
    spmm_mid<<<blocks, 256>>>(1, n_nodes);
    spmm_mid<<<blocks, 256>>>(2, n_nodes);
    spmm_last<<<blocks, 256>>>(uw, iw, num_users, n_nodes, out);
}